// round 12
// baseline (speedup 1.0000x reference)
#include <cuda_runtime.h>
#include <cstdint>
#include <cstddef>

// Problem dims
#define BB 128
#define TT 64
#define EE 300
#define HH 2048
#define G4 8192          // 4*H
#define TOK 8192         // T*B

// Packed-chunk geometry for the recurrent GEMM
#define CHUNK 64                     // K elements per pipeline stage
#define NCHUNK (HH / CHUNK)          // 32
#define A_CH_FLOATS (BB * CHUNK)     // 8192 floats per A chunk
#define B_CH_FLOATS (64 * CHUNK)     // 4096 floats per B chunk (16KB)
#define NSTAGE 4
// smem: max(4 B-stages = 65536 B, epilogue 2x[128][68] = 69632 B)
#define SMEM_BYTES 69632

// Device scratch (allocation-free rule: static __device__ globals)
__device__ float g_Gih[(size_t)TOK * G4];            // 256 MB, layout ((t*128+cta)*128+b)*64 + gate*16 + c
__device__ float g_Wpack[(size_t)128 * NCHUNK * B_CH_FLOATS]; // 64 MB tf32-rounded, fragment-packed
__device__ float g_hpack[2][BB * HH];                // fragment-packed, tf32-rounded hidden state
__device__ float g_c[BB * HH];                       // cell state (fp32, plain [b][h])

// ---------------------------------------------------------------------------
__device__ __forceinline__ uint32_t f2tf(float f) {
    uint32_t u;
    asm("cvt.rna.tf32.f32 %0, %1;" : "=r"(u) : "f"(f));
    return u;
}

__device__ __forceinline__ void mma_tf32(float* d, uint32_t a0, uint32_t a1, uint32_t a2, uint32_t a3,
                                         uint32_t b0, uint32_t b1) {
    asm volatile(
        "mma.sync.aligned.m16n8k8.row.col.f32.tf32.tf32.f32 "
        "{%0,%1,%2,%3}, {%4,%5,%6,%7}, {%8,%9}, {%0,%1,%2,%3};\n"
        : "+f"(d[0]), "+f"(d[1]), "+f"(d[2]), "+f"(d[3])
        : "r"(a0), "r"(a1), "r"(a2), "r"(a3), "r"(b0), "r"(b1));
}

__device__ __forceinline__ void cp16(float* s, const float* g) {
    uint32_t sa = (uint32_t)__cvta_generic_to_shared(s);
    asm volatile("cp.async.cg.shared.global [%0], [%1], 16;\n" :: "r"(sa), "l"(g));
}
#define CP_COMMIT() asm volatile("cp.async.commit_group;\n" ::: "memory")
#define CP_WAIT(N)  asm volatile("cp.async.wait_group %0;\n" :: "n"(N) : "memory")

__device__ __forceinline__ float sigmoidf_(float x) {
    return 1.0f / (1.0f + __expf(-x));
}

// ---------------------------------------------------------------------------
// init: zero h0 (packed) and c0
// ---------------------------------------------------------------------------
__global__ void init_kernel() {
    int i = blockIdx.x * blockDim.x + threadIdx.x;
    if (i < BB * HH) {
        g_hpack[0][i] = 0.0f;
        g_c[i]        = 0.0f;
    }
}

// ---------------------------------------------------------------------------
// Pack W_hh into tf32-rounded, B-fragment order.
// Layout: [cta 128][kc 32][q 8][pair 4][lane 32][slot 4]
// ---------------------------------------------------------------------------
__global__ __launch_bounds__(256) void pack_w_kernel(const float* __restrict__ w_hh) {
    int p4 = blockIdx.x * blockDim.x + threadIdx.x;   // 0 .. 4194303
    int lane = p4 & 31;  int rest = p4 >> 5;
    int pair = rest & 3; rest >>= 2;
    int q    = rest & 7; rest >>= 3;
    int kc   = rest & 31;
    int cta  = rest >> 5;
    int g  = lane >> 2;
    int tg = lane & 3;

    float4 v;
    float* vv = (float*)&v;
    #pragma unroll
    for (int which = 0; which < 2; which++) {
        int j = (pair * 2 + which) * 8 + g;
        int wrow = (j >> 4) * HH + cta * 16 + (j & 15);
        #pragma unroll
        for (int khalf = 0; khalf < 2; khalf++) {
            int k = kc * CHUNK + q * 8 + khalf * 4 + tg;
            float x = w_hh[(size_t)wrow * HH + k];
            vv[which * 2 + khalf] = __uint_as_float(f2tf(x));
        }
    }
    *reinterpret_cast<float4*>(&g_Wpack[(size_t)p4 * 4]) = v;
}

// ---------------------------------------------------------------------------
// Phase 1: G_ih[r][N] = embed[input[r]] @ W_ih^T + b_ih + b_hh
// ---------------------------------------------------------------------------
__global__ __launch_bounds__(256) void phase1_kernel(
    const int*   __restrict__ input,
    const float* __restrict__ embed,
    const float* __restrict__ w_ih,
    const float* __restrict__ b_ih,
    const float* __restrict__ b_hh)
{
    __shared__ float sbuf[9216];   // As: 128x36, Bs: 128x36
    __shared__ int   ids[128];
    float* As = sbuf;
    float* Bs = sbuf + 4608;

    const int tid  = threadIdx.x;
    const int lane = tid & 31;
    const int warp = tid >> 5;
    const int wm   = warp >> 1;
    const int wn   = warp & 1;
    const int g    = lane >> 2;
    const int tg   = lane & 3;

    const int n0 = blockIdx.x * 128;
    const int r0 = blockIdx.y * 128;

    if (tid < 128) {
        int r = r0 + tid;
        int b = r & 127;
        int t = r >> 7;
        ids[tid] = input[b * TT + t];
    }

    float acc[2][8][4];
    #pragma unroll
    for (int mi = 0; mi < 2; mi++)
        #pragma unroll
        for (int ni = 0; ni < 8; ni++)
            #pragma unroll
            for (int e = 0; e < 4; e++) acc[mi][ni][e] = 0.0f;

    for (int kc = 0; kc < 320; kc += 32) {
        __syncthreads();
        #pragma unroll
        for (int p = 0; p < 4; p++) {
            int v   = p * 256 + tid;
            int row = v >> 3;
            int k4  = (v & 7) * 4;
            int kk  = kc + k4;
            float4 val = make_float4(0.f, 0.f, 0.f, 0.f);
            if (kk <= 296) {
                val = *reinterpret_cast<const float4*>(embed + (size_t)ids[row] * EE + kk);
            }
            *reinterpret_cast<float4*>(&As[row * 36 + k4]) = val;
        }
        #pragma unroll
        for (int p = 0; p < 4; p++) {
            int v   = p * 256 + tid;
            int row = v >> 3;
            int k4  = (v & 7) * 4;
            int kk  = kc + k4;
            float4 val = make_float4(0.f, 0.f, 0.f, 0.f);
            if (kk <= 296) {
                val = *reinterpret_cast<const float4*>(w_ih + (size_t)(n0 + row) * EE + kk);
            }
            *reinterpret_cast<float4*>(&Bs[row * 36 + k4]) = val;
        }
        __syncthreads();

        #pragma unroll
        for (int q = 0; q < 4; q++) {
            int kq = q * 8;
            uint32_t af[2][4];
            #pragma unroll
            for (int mi = 0; mi < 2; mi++) {
                int rb = wm * 32 + mi * 16;
                af[mi][0] = f2tf(As[(rb + g    ) * 36 + kq + tg    ]);
                af[mi][1] = f2tf(As[(rb + g + 8) * 36 + kq + tg    ]);
                af[mi][2] = f2tf(As[(rb + g    ) * 36 + kq + tg + 4]);
                af[mi][3] = f2tf(As[(rb + g + 8) * 36 + kq + tg + 4]);
            }
            uint32_t bf[8][2];
            #pragma unroll
            for (int ni = 0; ni < 8; ni++) {
                int cb = wn * 64 + ni * 8;
                bf[ni][0] = f2tf(Bs[(cb + g) * 36 + kq + tg    ]);
                bf[ni][1] = f2tf(Bs[(cb + g) * 36 + kq + tg + 4]);
            }
            #pragma unroll
            for (int mi = 0; mi < 2; mi++)
                #pragma unroll
                for (int ni = 0; ni < 8; ni++)
                    mma_tf32(acc[mi][ni], af[mi][0], af[mi][1], af[mi][2], af[mi][3],
                             bf[ni][0], bf[ni][1]);
        }
    }

    #pragma unroll
    for (int mi = 0; mi < 2; mi++) {
        #pragma unroll
        for (int ni = 0; ni < 8; ni++) {
            #pragma unroll
            for (int h2 = 0; h2 < 2; h2++) {
                int row = r0 + wm * 32 + mi * 16 + g + h2 * 8;
                int t = row >> 7;
                int b = row & 127;
                int col = n0 + wn * 64 + ni * 8 + 2 * tg;
                int cta = (col & (HH - 1)) >> 4;
                int j   = (col >> 11) * 16 + (col & 15);
                float v0 = acc[mi][ni][h2 * 2 + 0] + b_ih[col]     + b_hh[col];
                float v1 = acc[mi][ni][h2 * 2 + 1] + b_ih[col + 1] + b_hh[col + 1];
                size_t addr = ((size_t)(t * 128 + cta) * 128 + b) * 64 + j;
                *reinterpret_cast<float2*>(&g_Gih[addr]) = make_float2(v0, v1);
            }
        }
    }
}

// ---------------------------------------------------------------------------
// Step t: gates = G_ih[t] + h @ W_hh^T ; fused LSTM cell update.
// 128 CTAs, 512 threads = 16 warps as 4(M) x 2(N) x 2(K-slice).
// A-fragments: DIRECT LDG.128 from the packed gmem image (L2-hot, 1MB),
//   register-prefetched one q ahead (prefetch crosses the chunk barrier).
// B-fragments: cp.async 4-stage smem pipeline (16KB stages) + LDS.128.
// This halves L1-port traffic vs the all-smem version.
// ---------------------------------------------------------------------------
__global__ __launch_bounds__(512, 1) void step_kernel(int t, float* __restrict__ d_out_opt)
{
    extern __shared__ float smem[];

    const float* __restrict__ h_in  = g_hpack[t & 1];
    float*       __restrict__ h_out = g_hpack[(t + 1) & 1];

    const int tid  = threadIdx.x;
    const int lane = tid & 31;
    const int warp = tid >> 5;        // 0..15
    const int wk   = warp & 1;        // 0..1  (K slice: q = wk*4 + qq)
    const int wn   = (warp >> 1) & 1; // 0..1  (N)
    const int wm   = warp >> 2;       // 0..3  (M)
    const int g    = lane >> 2;
    const int tg   = lane & 3;
    const int cta  = blockIdx.x;

    const float* __restrict__ wb = g_Wpack + (size_t)cta * (NCHUNK * B_CH_FLOATS);

    // B-stage loader: 4096 floats = 1024 float4, 512 threads -> 2 each
    auto load_b = [&](int s, int kc) {
        float* dst = smem + s * B_CH_FLOATS;
        const float* gb = wb + (size_t)kc * B_CH_FLOATS;
        cp16(dst + tid * 4,          gb + tid * 4);
        cp16(dst + (512 + tid) * 4,  gb + (512 + tid) * 4);
    };

    load_b(0, 0); CP_COMMIT();
    load_b(1, 1); CP_COMMIT();
    load_b(2, 2); CP_COMMIT();

    float acc[2][4][4];
    #pragma unroll
    for (int mi = 0; mi < 2; mi++)
        #pragma unroll
        for (int ni = 0; ni < 4; ni++)
            #pragma unroll
            for (int e = 0; e < 4; e++) acc[mi][ni][e] = 0.0f;

    // A prefetch: chunk 0, this warp's first q
    const float* __restrict__ hA = h_in + lane * 4;
    float4 aN0 = *reinterpret_cast<const float4*>(hA + ((0 * 8 + wk * 4) * 8 + wm * 2 + 0) * 128);
    float4 aN1 = *reinterpret_cast<const float4*>(hA + ((0 * 8 + wk * 4) * 8 + wm * 2 + 1) * 128);

    for (int kc = 0; kc < NCHUNK; kc++) {
        CP_WAIT(2);
        __syncthreads();
        if (kc + 3 < NCHUNK) load_b((kc + 3) & 3, kc + 3);
        CP_COMMIT();

        const float* SB = smem + (kc & 3) * B_CH_FLOATS + lane * 4;

        #pragma unroll
        for (int qq = 0; qq < 4; qq++) {
            int q = wk * 4 + qq;
            float4 a0 = aN0;
            float4 a1 = aN1;

            // prefetch next q's A (crosses chunk boundary; independent of smem pipe)
            if (!(kc == NCHUNK - 1 && qq == 3)) {
                int nkc = (qq == 3) ? kc + 1 : kc;
                int nq  = (qq == 3) ? wk * 4 : q + 1;
                aN0 = *reinterpret_cast<const float4*>(hA + ((nkc * 8 + nq) * 8 + wm * 2 + 0) * 128);
                aN1 = *reinterpret_cast<const float4*>(hA + ((nkc * 8 + nq) * 8 + wm * 2 + 1) * 128);
            }

            float4 bA = *reinterpret_cast<const float4*>(SB + (q * 4 + wn * 2 + 0) * 128);
            float4 bB = *reinterpret_cast<const float4*>(SB + (q * 4 + wn * 2 + 1) * 128);

            uint32_t a0x = __float_as_uint(a0.x), a0y = __float_as_uint(a0.y),
                     a0z = __float_as_uint(a0.z), a0w = __float_as_uint(a0.w);
            uint32_t a1x = __float_as_uint(a1.x), a1y = __float_as_uint(a1.y),
                     a1z = __float_as_uint(a1.z), a1w = __float_as_uint(a1.w);

            mma_tf32(acc[0][0], a0x, a0y, a0z, a0w, __float_as_uint(bA.x), __float_as_uint(bA.y));
            mma_tf32(acc[1][0], a1x, a1y, a1z, a1w, __float_as_uint(bA.x), __float_as_uint(bA.y));
            mma_tf32(acc[0][1], a0x, a0y, a0z, a0w, __float_as_uint(bA.z), __float_as_uint(bA.w));
            mma_tf32(acc[1][1], a1x, a1y, a1z, a1w, __float_as_uint(bA.z), __float_as_uint(bA.w));
            mma_tf32(acc[0][2], a0x, a0y, a0z, a0w, __float_as_uint(bB.x), __float_as_uint(bB.y));
            mma_tf32(acc[1][2], a1x, a1y, a1z, a1w, __float_as_uint(bB.x), __float_as_uint(bB.y));
            mma_tf32(acc[0][3], a0x, a0y, a0z, a0w, __float_as_uint(bB.z), __float_as_uint(bB.w));
            mma_tf32(acc[1][3], a1x, a1y, a1z, a1w, __float_as_uint(bB.z), __float_as_uint(bB.w));
        }
    }

    // ---- epilogue: both K-slices dump accumulators to smem, then fuse ----
    __syncthreads();
    float* Gb = smem + wk * 8704;           // two [128][68] images
    #pragma unroll
    for (int mi = 0; mi < 2; mi++) {
        #pragma unroll
        for (int ni = 0; ni < 4; ni++) {
            #pragma unroll
            for (int rh = 0; rh < 2; rh++) {
                int row = wm * 32 + mi * 16 + g + rh * 8;
                int col = wn * 32 + ni * 8 + 2 * tg;
                *reinterpret_cast<float2*>(&Gb[row * 68 + col]) =
                    make_float2(acc[mi][ni][rh * 2 + 0], acc[mi][ni][rh * 2 + 1]);
            }
        }
    }
    __syncthreads();

    const float* __restrict__ G0 = smem;
    const float* __restrict__ G1 = smem + 8704;
    const float* __restrict__ gih = g_Gih + ((size_t)(t * 128 + cta) * 128) * 64;
    const int n0 = cta * 16;

    #pragma unroll
    for (int p = 0; p < 4; p++) {
        int idx = p * 512 + tid;
        int c   = idx & 15;
        int b   = idx >> 4;
        const float* base = gih + b * 64;
        int r68 = b * 68;

        float iv = G0[r68 +      c] + G1[r68 +      c] + base[     c];
        float fv = G0[r68 + 16 + c] + G1[r68 + 16 + c] + base[16 + c];
        float gv = G0[r68 + 32 + c] + G1[r68 + 32 + c] + base[32 + c];
        float ov = G0[r68 + 48 + c] + G1[r68 + 48 + c] + base[48 + c];

        float ig = sigmoidf_(iv);
        float fg = sigmoidf_(fv);
        float gg = tanhf(gv);
        float og = sigmoidf_(ov);

        int hcol = n0 + c;
        float cold = g_c[b * HH + hcol];
        float cn = fg * cold + ig * gg;
        g_c[b * HH + hcol] = cn;
        float hn = og * tanhf(cn);

        // packed store for the next step's A operand (tf32-rounded)
        int kc2   = hcol >> 6;
        int q2    = (hcol >> 3) & 7;
        int tg2   = hcol & 3;
        int khalf = (hcol >> 2) & 1;
        int mt    = b >> 4;
        int g2    = b & 7;
        int rh    = (b >> 3) & 1;
        int lane2 = g2 * 4 + tg2;
        int slot  = khalf * 2 + rh;
        h_out[((kc2 * 8 + q2) * 8 + mt) * 128 + lane2 * 4 + slot] = __uint_as_float(f2tf(hn));

        if (d_out_opt) d_out_opt[b * HH + hcol] = hn;
    }
}

// ---------------------------------------------------------------------------
extern "C" void kernel_launch(void* const* d_in, const int* in_sizes, int n_in,
                              void* d_out, int out_size) {
    (void)in_sizes; (void)n_in; (void)out_size;
    const int*   input = (const int*)  d_in[0];
    const float* embed = (const float*)d_in[1];
    const float* w_ih  = (const float*)d_in[2];
    const float* w_hh  = (const float*)d_in[3];
    const float* b_ih  = (const float*)d_in[4];
    const float* b_hh  = (const float*)d_in[5];
    float* out = (float*)d_out;

    static int smem_set = 0;
    if (!smem_set) {
        cudaFuncSetAttribute(step_kernel, cudaFuncAttributeMaxDynamicSharedMemorySize, SMEM_BYTES);
        smem_set = 1;
    }

    init_kernel<<<(BB * HH + 255) / 256, 256>>>();
    pack_w_kernel<<<16384, 256>>>(w_hh);
    phase1_kernel<<<dim3(64, 64), 256>>>(input, embed, w_ih, b_ih, b_hh);
    for (int t = 0; t < TT; t++) {
        step_kernel<<<128, 512, SMEM_BYTES>>>(t, (t == TT - 1) ? out : nullptr);
    }
}

// round 16
// speedup vs baseline: 1.0325x; 1.0325x over previous
#include <cuda_runtime.h>
#include <cstdint>
#include <cstddef>

// Problem dims
#define BB 128
#define TT 64
#define EE 300
#define HH 2048
#define G4 8192          // 4*H
#define TOK 8192         // T*B

// Packed-chunk geometry for the recurrent GEMM
#define CHUNK 64                     // K elements per pipeline stage
#define NCHUNK (HH / CHUNK)          // 32
#define A_CH_FLOATS (BB * CHUNK)     // 8192 floats per A chunk (32KB)
#define B_CH_FLOATS (64 * CHUNK)     // 4096 floats per B chunk (16KB)
#define STAGE_FLOATS (A_CH_FLOATS + B_CH_FLOATS)  // 12288
#define NSTAGE 4
#define SMEM_BYTES (NSTAGE * STAGE_FLOATS * 4)    // 196608

// Device scratch (allocation-free rule: static __device__ globals)
__device__ float g_Gih[(size_t)TOK * G4];            // 256 MB, layout ((t*128+cta)*128+b)*64 + gate*16 + c
__device__ float g_Wpack[(size_t)128 * NCHUNK * B_CH_FLOATS]; // 64 MB tf32-rounded, fragment-packed
__device__ float g_hpack[2][BB * HH];                // fragment-packed, tf32-rounded hidden state
__device__ float g_c[BB * HH];                       // cell state (fp32, plain [b][h])

// ---------------------------------------------------------------------------
__device__ __forceinline__ uint32_t f2tf(float f) {
    uint32_t u;
    asm("cvt.rna.tf32.f32 %0, %1;" : "=r"(u) : "f"(f));
    return u;
}

__device__ __forceinline__ void mma_tf32(float* d, uint32_t a0, uint32_t a1, uint32_t a2, uint32_t a3,
                                         uint32_t b0, uint32_t b1) {
    asm volatile(
        "mma.sync.aligned.m16n8k8.row.col.f32.tf32.tf32.f32 "
        "{%0,%1,%2,%3}, {%4,%5,%6,%7}, {%8,%9}, {%0,%1,%2,%3};\n"
        : "+f"(d[0]), "+f"(d[1]), "+f"(d[2]), "+f"(d[3])
        : "r"(a0), "r"(a1), "r"(a2), "r"(a3), "r"(b0), "r"(b1));
}

// cp.async with L2 evict_last policy (keeps W resident across the Gih stream)
__device__ __forceinline__ void cp16_pin(float* s, const float* g, uint64_t pol) {
    uint32_t sa = (uint32_t)__cvta_generic_to_shared(s);
    asm volatile("cp.async.cg.shared.global.L2::cache_hint [%0], [%1], 16, %2;\n"
                 :: "r"(sa), "l"(g), "l"(pol));
}
#define CP_COMMIT() asm volatile("cp.async.commit_group;\n" ::: "memory")
#define CP_WAIT(N)  asm volatile("cp.async.wait_group %0;\n" :: "n"(N) : "memory")

__device__ __forceinline__ uint64_t mk_evict_last() {
    uint64_t p;
    asm("createpolicy.fractional.L2::evict_last.b64 %0, 1.0;" : "=l"(p));
    return p;
}

__device__ __forceinline__ float sigmoidf_(float x) {
    return 1.0f / (1.0f + __expf(-x));
}

// ---------------------------------------------------------------------------
// init: zero h0 (packed) and c0
// ---------------------------------------------------------------------------
__global__ void init_kernel() {
    int i = blockIdx.x * blockDim.x + threadIdx.x;
    if (i < BB * HH) {
        g_hpack[0][i] = 0.0f;
        g_c[i]        = 0.0f;
    }
}

// ---------------------------------------------------------------------------
// Pack W_hh into tf32-rounded, B-fragment order.
// Layout: [cta 128][kc 32][q 8][pair 4][lane 32][slot 4]
// ---------------------------------------------------------------------------
__global__ __launch_bounds__(256) void pack_w_kernel(const float* __restrict__ w_hh) {
    int p4 = blockIdx.x * blockDim.x + threadIdx.x;   // 0 .. 4194303
    int lane = p4 & 31;  int rest = p4 >> 5;
    int pair = rest & 3; rest >>= 2;
    int q    = rest & 7; rest >>= 3;
    int kc   = rest & 31;
    int cta  = rest >> 5;
    int g  = lane >> 2;
    int tg = lane & 3;

    float4 v;
    float* vv = (float*)&v;
    #pragma unroll
    for (int which = 0; which < 2; which++) {
        int j = (pair * 2 + which) * 8 + g;
        int wrow = (j >> 4) * HH + cta * 16 + (j & 15);
        #pragma unroll
        for (int khalf = 0; khalf < 2; khalf++) {
            int k = kc * CHUNK + q * 8 + khalf * 4 + tg;
            float x = w_hh[(size_t)wrow * HH + k];
            vv[which * 2 + khalf] = __uint_as_float(f2tf(x));
        }
    }
    *reinterpret_cast<float4*>(&g_Wpack[(size_t)p4 * 4]) = v;
}

// ---------------------------------------------------------------------------
// Phase 1: G_ih[r][N] = embed[input[r]] @ W_ih^T + b_ih + b_hh
// ---------------------------------------------------------------------------
__global__ __launch_bounds__(256) void phase1_kernel(
    const int*   __restrict__ input,
    const float* __restrict__ embed,
    const float* __restrict__ w_ih,
    const float* __restrict__ b_ih,
    const float* __restrict__ b_hh)
{
    __shared__ float sbuf[9216];   // As: 128x36, Bs: 128x36
    __shared__ int   ids[128];
    float* As = sbuf;
    float* Bs = sbuf + 4608;

    const int tid  = threadIdx.x;
    const int lane = tid & 31;
    const int warp = tid >> 5;
    const int wm   = warp >> 1;
    const int wn   = warp & 1;
    const int g    = lane >> 2;
    const int tg   = lane & 3;

    const int n0 = blockIdx.x * 128;
    const int r0 = blockIdx.y * 128;

    if (tid < 128) {
        int r = r0 + tid;
        int b = r & 127;
        int t = r >> 7;
        ids[tid] = input[b * TT + t];
    }

    float acc[2][8][4];
    #pragma unroll
    for (int mi = 0; mi < 2; mi++)
        #pragma unroll
        for (int ni = 0; ni < 8; ni++)
            #pragma unroll
            for (int e = 0; e < 4; e++) acc[mi][ni][e] = 0.0f;

    for (int kc = 0; kc < 320; kc += 32) {
        __syncthreads();
        #pragma unroll
        for (int p = 0; p < 4; p++) {
            int v   = p * 256 + tid;
            int row = v >> 3;
            int k4  = (v & 7) * 4;
            int kk  = kc + k4;
            float4 val = make_float4(0.f, 0.f, 0.f, 0.f);
            if (kk <= 296) {
                val = *reinterpret_cast<const float4*>(embed + (size_t)ids[row] * EE + kk);
            }
            *reinterpret_cast<float4*>(&As[row * 36 + k4]) = val;
        }
        #pragma unroll
        for (int p = 0; p < 4; p++) {
            int v   = p * 256 + tid;
            int row = v >> 3;
            int k4  = (v & 7) * 4;
            int kk  = kc + k4;
            float4 val = make_float4(0.f, 0.f, 0.f, 0.f);
            if (kk <= 296) {
                val = *reinterpret_cast<const float4*>(w_ih + (size_t)(n0 + row) * EE + kk);
            }
            *reinterpret_cast<float4*>(&Bs[row * 36 + k4]) = val;
        }
        __syncthreads();

        #pragma unroll
        for (int q = 0; q < 4; q++) {
            int kq = q * 8;
            uint32_t af[2][4];
            #pragma unroll
            for (int mi = 0; mi < 2; mi++) {
                int rb = wm * 32 + mi * 16;
                af[mi][0] = f2tf(As[(rb + g    ) * 36 + kq + tg    ]);
                af[mi][1] = f2tf(As[(rb + g + 8) * 36 + kq + tg    ]);
                af[mi][2] = f2tf(As[(rb + g    ) * 36 + kq + tg + 4]);
                af[mi][3] = f2tf(As[(rb + g + 8) * 36 + kq + tg + 4]);
            }
            uint32_t bf[8][2];
            #pragma unroll
            for (int ni = 0; ni < 8; ni++) {
                int cb = wn * 64 + ni * 8;
                bf[ni][0] = f2tf(Bs[(cb + g) * 36 + kq + tg    ]);
                bf[ni][1] = f2tf(Bs[(cb + g) * 36 + kq + tg + 4]);
            }
            #pragma unroll
            for (int mi = 0; mi < 2; mi++)
                #pragma unroll
                for (int ni = 0; ni < 8; ni++)
                    mma_tf32(acc[mi][ni], af[mi][0], af[mi][1], af[mi][2], af[mi][3],
                             bf[ni][0], bf[ni][1]);
        }
    }

    #pragma unroll
    for (int mi = 0; mi < 2; mi++) {
        #pragma unroll
        for (int ni = 0; ni < 8; ni++) {
            #pragma unroll
            for (int h2 = 0; h2 < 2; h2++) {
                int row = r0 + wm * 32 + mi * 16 + g + h2 * 8;
                int t = row >> 7;
                int b = row & 127;
                int col = n0 + wn * 64 + ni * 8 + 2 * tg;
                int cta = (col & (HH - 1)) >> 4;
                int j   = (col >> 11) * 16 + (col & 15);
                float v0 = acc[mi][ni][h2 * 2 + 0] + b_ih[col]     + b_hh[col];
                float v1 = acc[mi][ni][h2 * 2 + 1] + b_ih[col + 1] + b_hh[col + 1];
                size_t addr = ((size_t)(t * 128 + cta) * 128 + b) * 64 + j;
                // streaming store: don't let the Gih stream pollute L2
                __stcs(reinterpret_cast<float2*>(&g_Gih[addr]), make_float2(v0, v1));
            }
        }
    }
}

// ---------------------------------------------------------------------------
// Step t: gates = G_ih[t] + h @ W_hh^T ; fused LSTM cell update.
// 128 CTAs, 512 threads = 16 warps as 4(M) x 2(N) x 2(K-slice)  [round-9 best]
// + L2 evict_last policy on all cp.async fills (pins W in L2)
// + __ldcs streaming reads of the Gih stream (evict-first).
// ---------------------------------------------------------------------------
__global__ __launch_bounds__(512) void step_kernel(int t, float* __restrict__ d_out_opt)
{
    extern __shared__ float smem[];

    const float* __restrict__ h_in  = g_hpack[t & 1];
    float*       __restrict__ h_out = g_hpack[(t + 1) & 1];

    const int tid  = threadIdx.x;
    const int lane = tid & 31;
    const int warp = tid >> 5;      // 0..15
    const int wm   = warp >> 2;     // 0..3  (M)
    const int wn   = (warp >> 1) & 1; // 0..1 (N)
    const int wk   = warp & 1;      // 0..1  (K slice)
    const int g    = lane >> 2;
    const int tg   = lane & 3;
    const int cta  = blockIdx.x;

    const uint64_t pol = mk_evict_last();
    const float* __restrict__ wb = g_Wpack + (size_t)cta * (NCHUNK * B_CH_FLOATS);

    auto load_stage = [&](int s, int kc) {
        float* dst = smem + s * STAGE_FLOATS;
        const float* ga = h_in + (size_t)kc * A_CH_FLOATS;
        const float* gb = wb + (size_t)kc * B_CH_FLOATS;
        #pragma unroll
        for (int i = 0; i < A_CH_FLOATS / (512 * 4); i++)   // 4
            cp16_pin(dst + (i * 512 + tid) * 4, ga + (i * 512 + tid) * 4, pol);
        #pragma unroll
        for (int i = 0; i < B_CH_FLOATS / (512 * 4); i++)   // 2
            cp16_pin(dst + A_CH_FLOATS + (i * 512 + tid) * 4, gb + (i * 512 + tid) * 4, pol);
    };

    load_stage(0, 0); CP_COMMIT();
    load_stage(1, 1); CP_COMMIT();
    load_stage(2, 2); CP_COMMIT();

    float acc[2][4][4];
    #pragma unroll
    for (int mi = 0; mi < 2; mi++)
        #pragma unroll
        for (int ni = 0; ni < 4; ni++)
            #pragma unroll
            for (int e = 0; e < 4; e++) acc[mi][ni][e] = 0.0f;

    for (int kc = 0; kc < NCHUNK; kc++) {
        CP_WAIT(2);
        __syncthreads();
        if (kc + 3 < NCHUNK) load_stage((kc + 3) & 3, kc + 3);
        CP_COMMIT();

        const float* S = smem + (kc & 3) * STAGE_FLOATS;
        const float* SA = S + lane * 4;
        const float* SB = S + A_CH_FLOATS + lane * 4;

        #pragma unroll
        for (int qq = 0; qq < 4; qq++) {
            int q = wk * 4 + qq;
            float4 a0 = *reinterpret_cast<const float4*>(SA + (q * 8 + wm * 2 + 0) * 128);
            float4 a1 = *reinterpret_cast<const float4*>(SA + (q * 8 + wm * 2 + 1) * 128);
            float4 bA = *reinterpret_cast<const float4*>(SB + (q * 4 + wn * 2 + 0) * 128);
            float4 bB = *reinterpret_cast<const float4*>(SB + (q * 4 + wn * 2 + 1) * 128);

            uint32_t a0x = __float_as_uint(a0.x), a0y = __float_as_uint(a0.y),
                     a0z = __float_as_uint(a0.z), a0w = __float_as_uint(a0.w);
            uint32_t a1x = __float_as_uint(a1.x), a1y = __float_as_uint(a1.y),
                     a1z = __float_as_uint(a1.z), a1w = __float_as_uint(a1.w);

            mma_tf32(acc[0][0], a0x, a0y, a0z, a0w, __float_as_uint(bA.x), __float_as_uint(bA.y));
            mma_tf32(acc[1][0], a1x, a1y, a1z, a1w, __float_as_uint(bA.x), __float_as_uint(bA.y));
            mma_tf32(acc[0][1], a0x, a0y, a0z, a0w, __float_as_uint(bA.z), __float_as_uint(bA.w));
            mma_tf32(acc[1][1], a1x, a1y, a1z, a1w, __float_as_uint(bA.z), __float_as_uint(bA.w));
            mma_tf32(acc[0][2], a0x, a0y, a0z, a0w, __float_as_uint(bB.x), __float_as_uint(bB.y));
            mma_tf32(acc[1][2], a1x, a1y, a1z, a1w, __float_as_uint(bB.x), __float_as_uint(bB.y));
            mma_tf32(acc[0][3], a0x, a0y, a0z, a0w, __float_as_uint(bB.z), __float_as_uint(bB.w));
            mma_tf32(acc[1][3], a1x, a1y, a1z, a1w, __float_as_uint(bB.z), __float_as_uint(bB.w));
        }
    }

    // ---- epilogue: both K-slices dump accumulators to smem, then fuse ----
    __syncthreads();
    float* Gb = smem + wk * 8704;           // two [128][68] images
    #pragma unroll
    for (int mi = 0; mi < 2; mi++) {
        #pragma unroll
        for (int ni = 0; ni < 4; ni++) {
            #pragma unroll
            for (int rh = 0; rh < 2; rh++) {
                int row = wm * 32 + mi * 16 + g + rh * 8;
                int col = wn * 32 + ni * 8 + 2 * tg;
                *reinterpret_cast<float2*>(&Gb[row * 68 + col]) =
                    make_float2(acc[mi][ni][rh * 2 + 0], acc[mi][ni][rh * 2 + 1]);
            }
        }
    }
    __syncthreads();

    const float* __restrict__ G0 = smem;
    const float* __restrict__ G1 = smem + 8704;
    const float* __restrict__ gih = g_Gih + ((size_t)(t * 128 + cta) * 128) * 64;
    const int n0 = cta * 16;

    #pragma unroll
    for (int p = 0; p < 4; p++) {
        int idx = p * 512 + tid;
        int c   = idx & 15;
        int b   = idx >> 4;
        const float* base = gih + b * 64;
        int r68 = b * 68;

        // streaming (evict-first) reads of the Gih stream
        float iv = G0[r68 +      c] + G1[r68 +      c] + __ldcs(base +      c);
        float fv = G0[r68 + 16 + c] + G1[r68 + 16 + c] + __ldcs(base + 16 + c);
        float gv = G0[r68 + 32 + c] + G1[r68 + 32 + c] + __ldcs(base + 32 + c);
        float ov = G0[r68 + 48 + c] + G1[r68 + 48 + c] + __ldcs(base + 48 + c);

        float ig = sigmoidf_(iv);
        float fg = sigmoidf_(fv);
        float gg = tanhf(gv);
        float og = sigmoidf_(ov);

        int hcol = n0 + c;
        float cold = g_c[b * HH + hcol];
        float cn = fg * cold + ig * gg;
        g_c[b * HH + hcol] = cn;
        float hn = og * tanhf(cn);

        // packed store for the next step's A operand (tf32-rounded)
        int kc2   = hcol >> 6;
        int q2    = (hcol >> 3) & 7;
        int tg2   = hcol & 3;
        int khalf = (hcol >> 2) & 1;
        int mt    = b >> 4;
        int g2    = b & 7;
        int rh    = (b >> 3) & 1;
        int lane2 = g2 * 4 + tg2;
        int slot  = khalf * 2 + rh;
        h_out[((kc2 * 8 + q2) * 8 + mt) * 128 + lane2 * 4 + slot] = __uint_as_float(f2tf(hn));

        if (d_out_opt) d_out_opt[b * HH + hcol] = hn;
    }
}

// ---------------------------------------------------------------------------
extern "C" void kernel_launch(void* const* d_in, const int* in_sizes, int n_in,
                              void* d_out, int out_size) {
    (void)in_sizes; (void)n_in; (void)out_size;
    const int*   input = (const int*)  d_in[0];
    const float* embed = (const float*)d_in[1];
    const float* w_ih  = (const float*)d_in[2];
    const float* w_hh  = (const float*)d_in[3];
    const float* b_ih  = (const float*)d_in[4];
    const float* b_hh  = (const float*)d_in[5];
    float* out = (float*)d_out;

    static int smem_set = 0;
    if (!smem_set) {
        cudaFuncSetAttribute(step_kernel, cudaFuncAttributeMaxDynamicSharedMemorySize, SMEM_BYTES);
        smem_set = 1;
    }

    init_kernel<<<(BB * HH + 255) / 256, 256>>>();
    pack_w_kernel<<<16384, 256>>>(w_hh);
    phase1_kernel<<<dim3(64, 64), 256>>>(input, embed, w_ih, b_ih, b_hh);
    for (int t = 0; t < TT; t++) {
        step_kernel<<<128, 512, SMEM_BYTES>>>(t, (t == TT - 1) ? out : nullptr);
    }
}